// round 15
// baseline (speedup 1.0000x reference)
#include <cuda_runtime.h>
#include <math.h>

#define N_NODES 20000
#define N_EDGES 320000

// ---------------- scratch (device globals) ----------------
// g_sv per node: s[0:64], v planar: 64 + 64*i + u
__device__ float g_sv[N_NODES * 256];
// g_agg per node, INTERLEAVED: [u][8] with components {A, D, B0, B1, B2, C0, C1, C2}
__device__ float g_agg[N_NODES * 512];
__device__ float g_gate[N_NODES * 64];
// CSR-sort by dst
__device__ int g_cnt[N_NODES];
__device__ int g_cur[N_NODES];
__device__ int g_eid[N_EDGES];

__device__ __forceinline__ float silu_n(float x) {
    return 1.679177f * x * (1.0f / (1.0f + __expf(-x)));
}

// ---------------- f32x2 packed-FMA helpers (Blackwell FFMA2) ----------------
typedef unsigned long long u64t;
__device__ __forceinline__ u64t pkdup(float v) {
    u64t r; asm("mov.b64 %0, {%1, %1};" : "=l"(r) : "f"(v)); return r;
}
__device__ __forceinline__ void fma2(u64t& d, u64t a, u64t b) {
    asm("fma.rn.f32x2 %0, %1, %2, %0;" : "+l"(d) : "l"(a), "l"(b));
}
__device__ __forceinline__ float2 up2(u64t v) {
    float2 r; asm("mov.b64 {%0, %1}, %2;" : "=f"(r.x), "=f"(r.y) : "l"(v)); return r;
}
__device__ __forceinline__ void red4(float* p, float a, float b, float c, float d) {
    asm volatile("red.global.add.v4.f32 [%0], {%1, %2, %3, %4};"
                 :: "l"(p), "f"(a), "f"(b), "f"(c), "f"(d) : "memory");
}

// ---------------- K1: lin1, persistent blocks, weights staged in smem ----------------
__global__ void __launch_bounds__(256)
k1_lin1(const float* __restrict__ ns, const float* __restrict__ nv,
        const float* __restrict__ W1s, const float* __restrict__ W1v) {
    __shared__ float sWs[4096];
    __shared__ float sWv[4096];
    __shared__ float sIn[4][256];
    int tid = threadIdx.x;
    for (int i = tid; i < 4096; i += 256) {
        sWs[i] = W1s[i] * 0.125f;
        sWv[i] = W1v[i] * 0.125f;
    }
    __syncthreads();
    int w = tid & 63, q = tid >> 6;
    const int ntile = N_NODES / 4;

    for (int tile = blockIdx.x; tile < ntile; tile += gridDim.x) {
        int n0 = tile * 4;
        __syncthreads();
        for (int idx = tid; idx < 1024; idx += 256) {
            int q2 = idx >> 8, r = idx & 255;
            sIn[q2][r] = (r < 64) ? ns[(size_t)(n0 + q2) * 64 + r]
                                  : nv[(size_t)(n0 + q2) * 192 + (r - 64)];
        }
        __syncthreads();
        const float* si = sIn[q];
        float as = 0.f, a0 = 0.f, a1 = 0.f, a2 = 0.f;
#pragma unroll 4
        for (int u = 0; u < 64; u++) {
            float ws = sWs[u * 64 + w];
            float wv = sWv[u * 64 + w];
            as += si[u] * ws;
            a0 += si[64 + 3 * u + 0] * wv;
            a1 += si[64 + 3 * u + 1] * wv;
            a2 += si[64 + 3 * u + 2] * wv;
        }
        float* o = g_sv + (size_t)(n0 + q) * 256;
        o[w] = as;
        o[64 + w] = a0;
        o[128 + w] = a1;
        o[192 + w] = a2;
    }
}

// ---------------- K2: zero the aggregation buffer ----------------
__global__ void k2_zero() {
    int i = blockIdx.x * blockDim.x + threadIdx.x;
    int stride = gridDim.x * blockDim.x;
    float4* p = (float4*)g_agg;
    const int n4 = N_NODES * 512 / 4;
    for (; i < n4; i += stride) p[i] = make_float4(0.f, 0.f, 0.f, 0.f);
}

// ---------------- CSR-sort build (dst-sorted edge permutation) ----------------
__global__ void kc_zero() {
    int i = blockIdx.x * blockDim.x + threadIdx.x;
    if (i < N_NODES) g_cnt[i] = 0;
}
__global__ void kc_count(const int* __restrict__ edst) {
    int e = blockIdx.x * blockDim.x + threadIdx.x;
    if (e < N_EDGES) {
        int d = min(max(edst[e], 0), N_NODES - 1);
        atomicAdd(&g_cnt[d], 1);
    }
}
__global__ void __launch_bounds__(1024) kc_scan() {
    __shared__ int part[1024];
    int tid = threadIdx.x;
    const int PER = 20;  // 1024*20 >= 20000
    int base = tid * PER;
    int s = 0;
    for (int i = 0; i < PER; i++) {
        int idx = base + i;
        if (idx < N_NODES) s += g_cnt[idx];
    }
    part[tid] = s;
    __syncthreads();
    for (int d = 1; d < 1024; d <<= 1) {
        int v = 0;
        if (tid >= d) v = part[tid - d];
        __syncthreads();
        if (tid >= d) part[tid] += v;
        __syncthreads();
    }
    int run = part[tid] - s;
    for (int i = 0; i < PER; i++) {
        int idx = base + i;
        if (idx < N_NODES) {
            g_cur[idx] = run;
            run += g_cnt[idx];
        }
    }
}
__global__ void kc_scatter(const int* __restrict__ edst) {
    int e = blockIdx.x * blockDim.x + threadIdx.x;
    if (e < N_EDGES) {
        int d = min(max(edst[e], 0), N_NODES - 1);
        int pos = atomicAdd(&g_cur[d], 1);
        g_eid[pos] = e;
    }
}

// ---------------- K3: fused edge MLP over dst-sorted edges + run-combined scatter ----------------
// smem floats: sW0 512 + sW1 4096 + sW2 16384 + 16 warps * 768 = 33280 -> 133120 B
#define K3_SMEM 133120
__global__ void __launch_bounds__(512, 1)
k3_edge(const float* __restrict__ esh, const float* __restrict__ emb,
        const int* __restrict__ esrc, const int* __restrict__ edst,
        const float* __restrict__ W0, const float* __restrict__ W1,
        const float* __restrict__ W2) {
    extern __shared__ float sm[];
    float* sW0 = sm;           // [8][64]   pre-scaled 1/sqrt(8)
    float* sW1 = sm + 512;     // [64][64]  pre-scaled 0.125
    float* sW2 = sm + 4608;    // [64][256] pre-scaled 0.125
    int tid = threadIdx.x;
    for (int i = tid; i < 512; i += 512)   sW0[i] = W0[i] * 0.35355339059327373f;
    for (int i = tid; i < 4096; i += 512)  sW1[i] = W1[i] * 0.125f;
    for (int i = tid; i < 16384; i += 512) sW2[i] = W2[i] * 0.125f;
    __syncthreads();

    int warp = tid >> 5, lane = tid & 31;
    float* pH  = sm + 20992 + warp * 768;  // [row 64][stride 10]
    float* pEB = pH + 640;                 // 64: emb for 8 edges
    float* pSH = pEB + 64;                 // 32: sh float4 for 8 edges
    int*   pIX = (int*)(pSH + 32);         // 24: eid[8], src[8], dst[8]

    const float inv_sqrt3 = 0.57735026918962576f;
    const int ntile = N_EDGES / 8;  // 40000
    int gw = blockIdx.x * 16 + warp;
    int gstride = gridDim.x * 16;

    for (int tile = gw; tile < ntile; tile += gstride) {
        int e0 = tile * 8;
        // ---- edge meta via dst-sorted permutation ----
        if (lane < 8) {
            int eid = __ldg(g_eid + e0 + lane);
            pIX[lane] = eid;
            pIX[8 + lane]  = min(max(__ldg(esrc + eid), 0), N_NODES - 1);
            pIX[16 + lane] = min(max(__ldg(edst + eid), 0), N_NODES - 1);
            ((float4*)pSH)[lane] = __ldg((const float4*)esh + eid);
        }
        __syncwarp();
        {
            int eA = pIX[lane >> 3];
            int eB = pIX[4 + (lane >> 3)];
            pEB[lane]      = __ldg(emb + (size_t)eA * 8 + (lane & 7));
            pEB[32 + lane] = __ldg(emb + (size_t)eB * 8 + (lane & 7));
        }
        __syncwarp();

        // ---- fc0: h0[j][e] (stride 10); lane computes j = lane, lane+32 ----
#pragma unroll
        for (int e = 0; e < 8; e++) {
            float eb[8];
#pragma unroll
            for (int b = 0; b < 8; b++) eb[b] = pEB[e * 8 + b];
#pragma unroll
            for (int jj = 0; jj < 2; jj++) {
                int j = lane + 32 * jj;
                float a = 0.f;
#pragma unroll
                for (int b = 0; b < 8; b++) a += eb[b] * sW0[b * 64 + j];
                pH[j * 10 + e] = silu_n(a);
            }
        }
        __syncwarp();

        // ---- fc1: j = lane, lane+32; edge-paired FFMA2 over all 8 edges ----
        u64t h1[2][4] = {{0ull,0ull,0ull,0ull},{0ull,0ull,0ull,0ull}};
#pragma unroll 4
        for (int k = 0; k < 64; k++) {
            u64t wd0 = pkdup(sW1[k * 64 + lane]);
            u64t wd1 = pkdup(sW1[k * 64 + lane + 32]);
#pragma unroll
            for (int ep = 0; ep < 4; ep++) {
                u64t hp = *(const u64t*)(pH + k * 10 + 2 * ep);
                fma2(h1[0][ep], wd0, hp);
                fma2(h1[1][ep], wd1, hp);
            }
        }
        __syncwarp();
#pragma unroll
        for (int kk = 0; kk < 2; kk++)
#pragma unroll
            for (int ep = 0; ep < 4; ep++) {
                float2 v = up2(h1[kk][ep]);
                pH[(lane + 32 * kk) * 10 + 2 * ep]     = silu_n(v.x);
                pH[(lane + 32 * kk) * 10 + 2 * ep + 1] = silu_n(v.y);
            }
        __syncwarp();

        // ---- fc2: lane owns c = lane + 32j (j=0..7); acc[j][edge-pair] ----
        u64t acc[8][4];
#pragma unroll
        for (int c = 0; c < 8; c++)
#pragma unroll
            for (int ep = 0; ep < 4; ep++) acc[c][ep] = 0ull;
#pragma unroll 2
        for (int k = 0; k < 64; k++) {
            u64t wd[8];
#pragma unroll
            for (int c = 0; c < 8; c++)
                wd[c] = pkdup(sW2[k * 256 + lane + 32 * c]);
#pragma unroll
            for (int ep = 0; ep < 4; ep++) {
                u64t hp = *(const u64t*)(pH + k * 10 + 2 * ep);
#pragma unroll
                for (int c = 0; c < 8; c++) fma2(acc[c][ep], wd[c], hp);
            }
        }
        __syncwarp();

        // ---- epilogue: run-combined accumulation (edges sorted by dst) ----
        float racc[2][8];
#pragma unroll
        for (int h = 0; h < 2; h++)
#pragma unroll
            for (int i = 0; i < 8; i++) racc[h][i] = 0.f;
        int cur = pIX[16];
#pragma unroll
        for (int e = 0; e < 8; e++) {
            int d = pIX[16 + e];
            if (d != cur) {  // warp-uniform branch
                float* ag = g_agg + (size_t)cur * 512;
                red4(ag + lane * 8,            racc[0][0], racc[0][1], racc[0][2], racc[0][3]);
                red4(ag + lane * 8 + 4,        racc[0][4], racc[0][5], racc[0][6], racc[0][7]);
                red4(ag + (lane + 32) * 8,     racc[1][0], racc[1][1], racc[1][2], racc[1][3]);
                red4(ag + (lane + 32) * 8 + 4, racc[1][4], racc[1][5], racc[1][6], racc[1][7]);
#pragma unroll
                for (int h = 0; h < 2; h++)
#pragma unroll
                    for (int i = 0; i < 8; i++) racc[h][i] = 0.f;
                cur = d;
            }
            int src = pIX[8 + e];
            float y0 = pSH[4 * e + 0], Y1 = pSH[4 * e + 1];
            float Y2 = pSH[4 * e + 2], Y3 = pSH[4 * e + 3];
            const float* sv = g_sv + (size_t)src * 256;
#pragma unroll
            for (int half = 0; half < 2; half++) {
                int u = lane + 32 * half;
                float2 tA = up2(acc[half][e >> 1]);
                float2 tB = up2(acc[half + 2][e >> 1]);
                float2 tC = up2(acc[half + 4][e >> 1]);
                float2 tD = up2(acc[half + 6][e >> 1]);
                float wA = (e & 1) ? tA.y : tA.x;
                float wB = (e & 1) ? tB.y : tB.x;
                float wC = (e & 1) ? tC.y : tC.x;
                float wD = (e & 1) ? tD.y : tD.x;
                float sA = __ldg(sv + u);
                float v0 = __ldg(sv + 64 + u);
                float v1 = __ldg(sv + 128 + u);
                float v2 = __ldg(sv + 192 + u);
                racc[half][0] += wA * sA * y0;
                racc[half][1] += wD * (v0 * Y1 + v1 * Y2 + v2 * Y3) * inv_sqrt3;
                float bs = wB * sA;
                racc[half][2] += bs * Y1;
                racc[half][3] += bs * Y2;
                racc[half][4] += bs * Y3;
                float cy = wC * y0;
                racc[half][5] += cy * v0;
                racc[half][6] += cy * v1;
                racc[half][7] += cy * v2;
            }
        }
        {   // final flush
            float* ag = g_agg + (size_t)cur * 512;
            red4(ag + lane * 8,            racc[0][0], racc[0][1], racc[0][2], racc[0][3]);
            red4(ag + lane * 8 + 4,        racc[0][4], racc[0][5], racc[0][6], racc[0][7]);
            red4(ag + (lane + 32) * 8,     racc[1][0], racc[1][1], racc[1][2], racc[1][3]);
            red4(ag + (lane + 32) * 8 + 4, racc[1][4], racc[1][5], racc[1][6], racc[1][7]);
        }
        __syncwarp();
    }
}

// ---------------- K4a: s_h = [agg_s | ns(x)attr] @ Wcat, gates + out_s ----------------
#define K4A_SMEM 221184
__global__ void __launch_bounds__(512)
k4a(const float* __restrict__ ns, const float* __restrict__ attr,
    const float* __restrict__ Wl2s, const float* __restrict__ Wscs,
    float* __restrict__ out) {
    extern __shared__ float sm[];
    float* sW = sm;            // [384][128], pre-scaled
    float* sOp = sW + 49152;   // [384][16]
    int tid = threadIdx.x;
    const float lin2n = 0.08838834764831845f;
    const float scn = 0.0625f;
    for (int i = tid; i < 16384; i += 512) sW[i] = Wl2s[i] * lin2n;
    for (int i = tid; i < 32768; i += 512) sW[16384 + i] = Wscs[i] * scn;
    __syncthreads();

    int w = tid & 127, nh = tid >> 7;
    const int ntile = N_NODES / 16;

    for (int tile = blockIdx.x; tile < ntile; tile += gridDim.x) {
        int n0 = tile * 16;
        {
            int k = tid & 127, q = tid >> 7;
            int src_idx = (k < 64) ? (k * 8) : ((k - 64) * 8 + 1);  // A at u*8, D at u*8+1
#pragma unroll
            for (int nn = 0; nn < 4; nn++) {
                int node = q * 4 + nn;
                sOp[k * 16 + node] = g_agg[(size_t)(n0 + node) * 512 + src_idx] * 0.0625f;
            }
            for (int idx = tid; idx < 4096; idx += 512) {
                int m = idx >> 4, node = idx & 15;
                sOp[(128 + m) * 16 + node] =
                    ns[(size_t)(n0 + node) * 64 + (m >> 2)] * attr[(size_t)(n0 + node) * 4 + (m & 3)];
            }
        }
        __syncthreads();

        u64t a01 = 0ull, a23 = 0ull;
#pragma unroll 4
        for (int k = 0; k < 384; k++) {
            u64t wd = pkdup(sW[k * 128 + w]);
            ulonglong2 op = *(const ulonglong2*)(sOp + k * 16 + nh * 4);
            fma2(a01, wd, op.x);
            fma2(a23, wd, op.y);
        }
        float2 r01 = up2(a01), r23 = up2(a23);
        float r[4] = {r01.x, r01.y, r23.x, r23.y};
#pragma unroll
        for (int j = 0; j < 4; j++) {
            int n = n0 + nh * 4 + j;
            float val = silu_n(r[j]);
            if (w < 64) out[(size_t)n * 256 + w] = val;
            else        g_gate[(size_t)n * 64 + (w - 64)] = val;
        }
        __syncthreads();
    }
}

// ---------------- K4b: v_h = [agg_v | nv(x)attr] @ Wvcat, gate + out_v ----------------
#define K4B_SMEM 147456
__global__ void __launch_bounds__(512)
k4b(const float* __restrict__ nv, const float* __restrict__ attr,
    const float* __restrict__ Wl2v, const float* __restrict__ Wscv,
    float* __restrict__ out) {
    extern __shared__ float sm[];
    float* sW = sm;            // [384][64], pre-scaled
    float* sOp = sW + 24576;   // [384][8 nodes][4]
    int tid = threadIdx.x;
    const float lin2n = 0.08838834764831845f;
    const float scn = 0.0625f;
    for (int i = tid; i < 8192; i += 512)  sW[i] = Wl2v[i] * lin2n;
    for (int i = tid; i < 16384; i += 512) sW[8192 + i] = Wscv[i] * scn;
    __syncthreads();

    int w = tid & 63, node = tid >> 6;
    const int ntile = N_NODES / 8;

    for (int tile = blockIdx.x; tile < ntile; tile += gridDim.x) {
        int n0 = tile * 8;
        for (int idx = tid; idx < 3072; idx += 512) {
            int k = idx >> 3, nd = idx & 7;
            int n = n0 + nd;
            float o0, o1, o2;
            if (k < 128) {
                int u = (k < 64) ? k : (k - 64);
                int base = u * 8 + ((k < 64) ? 2 : 5);  // B at u*8+2.., C at u*8+5..
                const float* p = g_agg + (size_t)n * 512 + base;
                o0 = p[0] * 0.0625f; o1 = p[1] * 0.0625f; o2 = p[2] * 0.0625f;
            } else {
                int m = k - 128;
                int u = m >> 2, v = m & 3;
                float av = attr[(size_t)n * 4 + v];
                const float* p = nv + (size_t)n * 192 + u * 3;
                o0 = p[0] * av; o1 = p[1] * av; o2 = p[2] * av;
            }
            *(float4*)(sOp + idx * 4) = make_float4(o0, o1, o2, 0.f);
        }
        __syncthreads();

        u64t a01 = 0ull;
        float a2 = 0.f;
#pragma unroll 4
        for (int k = 0; k < 384; k++) {
            float wk = sW[k * 64 + w];
            u64t wd = pkdup(wk);
            ulonglong2 op = *(const ulonglong2*)(sOp + (k * 8 + node) * 4);
            fma2(a01, wd, op.x);
            float2 t = up2(op.y);
            a2 += wk * t.x;
        }
        int n = n0 + node;
        float gate = g_gate[(size_t)n * 64 + w];
        float2 r = up2(a01);
        float* o = out + (size_t)n * 256 + 64 + 3 * w;
        o[0] = gate * r.x; o[1] = gate * r.y; o[2] = gate * a2;
        __syncthreads();
    }
}

// ---------------- launch ----------------
extern "C" void kernel_launch(void* const* d_in, const int* in_sizes, int n_in,
                              void* d_out, int out_size) {
    const float* node_scalars  = (const float*)d_in[0];
    const float* node_vectors  = (const float*)d_in[1];
    const float* node_attr     = (const float*)d_in[2];
    const float* edge_sh       = (const float*)d_in[3];
    const float* edge_embedded = (const float*)d_in[4];
    const int*   edge_src      = (const int*)d_in[5];
    const int*   edge_dst      = (const int*)d_in[6];
    const float* W_lin1_s      = (const float*)d_in[7];
    const float* W_lin1_v      = (const float*)d_in[8];
    const float* W_fc0         = (const float*)d_in[9];
    const float* W_fc1         = (const float*)d_in[10];
    const float* W_fc2         = (const float*)d_in[11];
    const float* W_lin2_s      = (const float*)d_in[12];
    const float* W_lin2_v      = (const float*)d_in[13];
    const float* W_sc_s        = (const float*)d_in[14];
    const float* W_sc_v        = (const float*)d_in[15];
    float* out = (float*)d_out;

    cudaFuncSetAttribute(k3_edge, cudaFuncAttributeMaxDynamicSharedMemorySize, K3_SMEM);
    cudaFuncSetAttribute(k4a, cudaFuncAttributeMaxDynamicSharedMemorySize, K4A_SMEM);
    cudaFuncSetAttribute(k4b, cudaFuncAttributeMaxDynamicSharedMemorySize, K4B_SMEM);

    kc_zero<<<40, 512>>>();
    kc_count<<<625, 512>>>(edge_dst);
    kc_scan<<<1, 1024>>>();
    kc_scatter<<<625, 512>>>(edge_dst);
    k1_lin1<<<148, 256>>>(node_scalars, node_vectors, W_lin1_s, W_lin1_v);
    k2_zero<<<1024, 256>>>();
    k3_edge<<<148, 512, K3_SMEM>>>(edge_sh, edge_embedded, edge_src, edge_dst,
                                   W_fc0, W_fc1, W_fc2);
    k4a<<<148, 512, K4A_SMEM>>>(node_scalars, node_attr, W_lin2_s, W_sc_s, out);
    k4b<<<148, 512, K4B_SMEM>>>(node_vectors, node_attr, W_lin2_v, W_sc_v, out);
}